// round 16
// baseline (speedup 1.0000x reference)
#include <cuda_runtime.h>
#include <cuda_fp16.h>
#include <cstdint>

#define NN 50000
#define NE 400000
#define HD 128

// ---------------- scratch (static device globals; no allocation) ----------------
__device__ __half g_hh0[NN * HD];
__device__ __half g_hl0[NN * HD];
__device__ __half g_hh1[NN * HD];
__device__ __half g_hl1[NN * HD];
__device__ float  g_AB0[NN * 256];      // A|B per node (ping)
__device__ float  g_AB1[NN * 256];      // A|B per node (pong)
__device__ __half g_WvT[256 * 128];     // W_msg rearranged, fp16, [n][k]
__device__ __half g_WpqT[256 * 128];    // We1 node part, fp16, [n][k]
__device__ __half g_WuT[128 * 256];     // W_upd, fp16, [n][k]
__device__ int g_cnt[NN];
__device__ int g_off[NN];
__device__ int g_cur[NN];
__device__ int g_esrc[NE];
__device__ int g_part[64];
__device__ int g_idx64;

__device__ __forceinline__ uint32_t smem_to_u32(const void* smem_ptr) {
    uint32_t addr;
    asm("{ .reg .u64 tmp; cvta.to.shared.u64 tmp, %1; cvt.u32.u64 %0, tmp; }"
        : "=r"(addr) : "l"(smem_ptr));
    return addr;
}

// ---------------- index dtype handling (int64 vs int32 edge_index) ----------------
__device__ __forceinline__ int get_idx(const void* ei, int pos) {
    if (g_idx64) return (int)((const long long*)ei)[pos];
    return ((const int*)ei)[pos];
}

// ---------------- detect + zero counters (merged) ----------------
__global__ void detect_zero_kernel(const void* ei) {
    int i = blockIdx.x * 256 + threadIdx.x;
    if (i < NN) g_cnt[i] = 0;
    if (i == 0) {
        const long long* p = (const long long*)ei;
        int ok = 1;
        for (int j = 0; j < 64; j++) {
            long long v = p[j];
            if (v < 0 || v >= NN) { ok = 0; break; }
        }
        g_idx64 = ok;
    }
}

__global__ void count_kernel(const void* ei) {
    int e = blockIdx.x * 256 + threadIdx.x;
    if (e < NE) atomicAdd(&g_cnt[get_idx(ei, NE + e)], 1);
}

// parallel 3-phase scan over g_cnt -> g_off/g_cur  (49 blocks of 1024)
__global__ void scan_part_kernel() {
    __shared__ int sd[1024];
    int t = threadIdx.x;
    int idx = blockIdx.x * 1024 + t;
    int v = (idx < NN) ? g_cnt[idx] : 0;
    sd[t] = v; __syncthreads();
    for (int o = 512; o; o >>= 1) {
        if (t < o) sd[t] += sd[t + o];
        __syncthreads();
    }
    if (t == 0) g_part[blockIdx.x] = sd[0];
}
__global__ void scan_top_kernel() {
    __shared__ int sd[64];
    int t = threadIdx.x;
    int v = (t < 49) ? g_part[t] : 0;
    sd[t] = v; __syncthreads();
    for (int o = 1; o < 64; o <<= 1) {
        int a = (t >= o) ? sd[t - o] : 0;
        __syncthreads();
        sd[t] += a;
        __syncthreads();
    }
    if (t < 49) g_part[t] = sd[t] - v;   // exclusive prefix
}
__global__ void scan_final_kernel() {
    __shared__ int sd[1024];
    int t = threadIdx.x;
    int idx = blockIdx.x * 1024 + t;
    int v = (idx < NN) ? g_cnt[idx] : 0;
    sd[t] = v; __syncthreads();
    for (int o = 1; o < 1024; o <<= 1) {
        int a = (t >= o) ? sd[t - o] : 0;
        __syncthreads();
        sd[t] += a;
        __syncthreads();
    }
    if (idx < NN) {
        int e = sd[t] - v + g_part[blockIdx.x];
        g_off[idx] = e;
        g_cur[idx] = e;
    }
}

__global__ void scatter_kernel(const void* ei) {
    int e = blockIdx.x * 256 + threadIdx.x;
    if (e < NE) {
        int d = get_idx(ei, NE + e);
        int pos = atomicAdd(&g_cur[d], 1);
        g_esrc[pos] = get_idx(ei, e);
    }
}

// ---------------- weight prep: fp16 transposed [n][k] tables (one kernel) ----------------
__global__ void prep_weights_kernel(const float* __restrict__ W_msg,
                                    const float* __restrict__ We1,
                                    const float* __restrict__ W_upd) {
    int i = blockIdx.x * 256 + threadIdx.x;   // 0 .. 98303
    if (i < 32768) {
        int n = i >> 7, k = i & 127;
        float v = (n < 128) ? W_msg[k * 128 + n] : W_msg[(128 + k) * 128 + (n - 128)];
        g_WvT[i] = __float2half_rn(v);
    } else if (i < 65536) {
        int j = i - 32768;
        int n = j >> 7, k = j & 127;
        float v = (n < 128) ? We1[k * 128 + n] : We1[(128 + k) * 128 + (n - 128)];
        g_WpqT[j] = __float2half_rn(v);
    } else if (i < 98304) {
        int j = i - 65536;
        int n = j >> 8, k = j & 255;
        g_WuT[j] = __float2half_rn(W_upd[k * 128 + n]);
    }
}

// ---------------- MMA primitives ----------------
__device__ __forceinline__ void ldsm_x4(uint32_t addr, uint32_t& r0, uint32_t& r1,
                                        uint32_t& r2, uint32_t& r3) {
    asm volatile("ldmatrix.sync.aligned.m8n8.x4.shared.b16 {%0,%1,%2,%3}, [%4];"
                 : "=r"(r0), "=r"(r1), "=r"(r2), "=r"(r3) : "r"(addr));
}
__device__ __forceinline__ void mma_f16(float* c, const uint32_t* a, uint32_t b0, uint32_t b1) {
    asm volatile(
        "mma.sync.aligned.m16n8k16.row.col.f32.f16.f16.f32 "
        "{%0,%1,%2,%3}, {%4,%5,%6,%7}, {%8,%9}, {%0,%1,%2,%3};"
        : "+f"(c[0]), "+f"(c[1]), "+f"(c[2]), "+f"(c[3])
        : "r"(a[0]), "r"(a[1]), "r"(a[2]), "r"(a[3]), "r"(b0), "r"(b1));
}
__device__ __forceinline__ void split_f16(float v, __half& h, __half& l) {
    h = __float2half_rn(v);
    l = __float2half_rn(v - __half2float(h));
}
__device__ __forceinline__ uint32_t pack_h2(__half a, __half b) {
    return (uint32_t)__half_as_ushort(a) | ((uint32_t)__half_as_ushort(b) << 16);
}

// ================= fused layer kernel (now also fuses aggregation) =================
// Per block: 128 node-rows.
//   P1 mode 0: hn = X0 @ W0 + b0   (encoder, K=16, scalar fp32, no relu)
//   P1 mode 1: hn = relu([h | agg] @ WuT + bupd)   (K=256, split-fp16 mma.sync)
//              chunks 0-3 (h) stream from planes; chunks 4-7 (agg) are GATHERED
//              in-kernel from ABin via CSR:  agg = (sum A[src] + cnt*(B+bmsg))*inv
//   hn tile -> smem (hi/lo fp16, XOR-256B swizzle) + gmem planes Hh/Hl
//   P2: ABout[128 rows][256] = hn @ Wt2   (two sequential 128-col halves)
#define ASTRIDE 40
#define LF_SH_HI  0                        // 128 x 256B swizzled (hi plane)
#define LF_SH_LO  32768                    // lo plane
#define LF_PAH(st) ((st) * 20480)          // P1 A-hi stage (overlaps SH; disjoint lifetime)
#define LF_PAL(st) ((st) * 20480 + 10240)  // P1 A-lo stage
#define LF_PB(st)  (65536 + (st) * 10240)  // B stages (P1 and P2, sequential use)
#define LF_X0  65536                       // mode 0: x tile transposed [16][128] f32
#define LF_W0  (65536 + 8192)              // mode 0: Wenc [16][128] f32
#define LF_SMEM (65536 + 20480)

__global__ void __launch_bounds__(256, 2) layer_fused_kernel(
    int mode,
    const float* __restrict__ X0, const float* __restrict__ W0, const float* __restrict__ b0,
    const __half* __restrict__ X1h, const __half* __restrict__ X1l,
    const __half* __restrict__ WuT, const float* __restrict__ bupd,
    const __half* __restrict__ Wt2,
    __half* __restrict__ Hh, __half* __restrict__ Hl,
    float* __restrict__ ABout, const float* __restrict__ ABin,
    const float* __restrict__ bmsg, int M)
{
    extern __shared__ __align__(16) char dsm[];
    const int bm = blockIdx.x * 128;
    const int t = threadIdx.x;
    const int lane = t & 31;
    const int wid = t >> 5;
    const int lrow = lane & 7, qq = lane >> 3;
    const int wm = wid >> 1, wn = wid & 1;
    const int m_off = wm * 32;
    const int n_off = wn * 64;
    const uint32_t sSHh = smem_to_u32(dsm + LF_SH_HI);
    const uint32_t sSHl = smem_to_u32(dsm + LF_SH_LO);

    if (mode == 0) {
        // ---- P1 encoder: scalar fp32, K=16, no relu ----
        float* Xs = (float*)(dsm + LF_X0);   // [16][128] transposed
        float* Ws = (float*)(dsm + LF_W0);   // [16][128]
        {
            int r = t >> 1, h8 = (t & 1) * 8;
            float4 v0 = make_float4(0.f, 0.f, 0.f, 0.f), v1 = v0;
            if (bm + r < M) {
                v0 = *(const float4*)(X0 + (size_t)(bm + r) * 16 + h8);
                v1 = *(const float4*)(X0 + (size_t)(bm + r) * 16 + h8 + 4);
            }
            Xs[(h8 + 0) * 128 + r] = v0.x; Xs[(h8 + 1) * 128 + r] = v0.y;
            Xs[(h8 + 2) * 128 + r] = v0.z; Xs[(h8 + 3) * 128 + r] = v0.w;
            Xs[(h8 + 4) * 128 + r] = v1.x; Xs[(h8 + 5) * 128 + r] = v1.y;
            Xs[(h8 + 6) * 128 + r] = v1.z; Xs[(h8 + 7) * 128 + r] = v1.w;
            int k = t >> 4, c = (t & 15) * 8;
            *(float4*)(Ws + k * 128 + c)     = *(const float4*)(W0 + (size_t)k * 128 + c);
            *(float4*)(Ws + k * 128 + c + 4) = *(const float4*)(W0 + (size_t)k * 128 + c + 4);
        }
        __syncthreads();
        const int tr = (t >> 4) * 8, tc = (t & 15) * 8;
        float acc[8][8];
#pragma unroll
        for (int i = 0; i < 8; i++)
#pragma unroll
            for (int j = 0; j < 8; j++) acc[i][j] = 0.f;
#pragma unroll
        for (int k = 0; k < 16; k++) {
            float xr[8], wc[8];
            *(float4*)(xr)     = *(const float4*)(Xs + k * 128 + tr);
            *(float4*)(xr + 4) = *(const float4*)(Xs + k * 128 + tr + 4);
            *(float4*)(wc)     = *(const float4*)(Ws + k * 128 + tc);
            *(float4*)(wc + 4) = *(const float4*)(Ws + k * 128 + tc + 4);
#pragma unroll
            for (int i = 0; i < 8; i++)
#pragma unroll
                for (int j = 0; j < 8; j++) acc[i][j] += xr[i] * wc[j];
        }
        float bj[8];
        *(float4*)(bj)     = *(const float4*)(b0 + tc);
        *(float4*)(bj + 4) = *(const float4*)(b0 + tc + 4);
#pragma unroll
        for (int i = 0; i < 8; i++) {
            int row = tr + i;
#pragma unroll
            for (int j = 0; j < 8; j += 2) {
                float v0 = acc[i][j] + bj[j], v1 = acc[i][j + 1] + bj[j + 1];
                __half h0, h1, l0, l1;
                split_f16(v0, h0, l0); split_f16(v1, h1, l1);
                uint32_t hp = pack_h2(h0, h1), lp = pack_h2(l0, l1);
                int col = tc + j;
                uint32_t byte = (uint32_t)row * 256 + (((uint32_t)col * 2) ^ (((uint32_t)(row & 7)) << 4));
                *(uint32_t*)(dsm + LF_SH_HI + byte) = hp;
                *(uint32_t*)(dsm + LF_SH_LO + byte) = lp;
                if (bm + row < M) {
                    *(uint32_t*)(Hh + (size_t)(bm + row) * 128 + col) = hp;
                    *(uint32_t*)(Hl + (size_t)(bm + row) * 128 + col) = lp;
                }
            }
        }
        __syncthreads();
    } else {
        // ---- P1 GNN layer: hn = relu([h | agg] @ WuT + bupd), K=256, pipelined ----
        int a_plane[4], a_r[4], a_kc[4];
#pragma unroll
        for (int i = 0; i < 4; i++) {
            int u = i * 256 + t;
            a_plane[i] = u >> 9;
            a_r[i] = (u >> 2) & 127;
            a_kc[i] = (u & 3) * 8;
        }
        int b_n[2], b_kc[2];
#pragma unroll
        for (int i = 0; i < 2; i++) {
            int u = i * 256 + t;
            b_n[i] = u >> 2;
            b_kc[i] = (u & 3) * 8;
        }
        uint4 av[4], bv[2];
        uint32_t* agw = (uint32_t*)av;   // agg gather results reuse av registers
        // prologue chunk 0 (h planes)
#pragma unroll
        for (int i = 0; i < 4; i++) {
            const __half* src = (a_plane[i] ? X1l : X1h) + (size_t)(bm + a_r[i]) * 128 + a_kc[i];
            av[i] = (bm + a_r[i] < M) ? *(const uint4*)src : make_uint4(0u, 0u, 0u, 0u);
        }
#pragma unroll
        for (int i = 0; i < 2; i++)
            bv[i] = *(const uint4*)(WuT + (size_t)b_n[i] * 256 + b_kc[i]);
#pragma unroll
        for (int i = 0; i < 4; i++)
            *(uint4*)((__half*)(dsm + (a_plane[i] ? LF_PAL(0) : LF_PAH(0))) + a_r[i] * ASTRIDE + a_kc[i]) = av[i];
#pragma unroll
        for (int i = 0; i < 2; i++)
            *(uint4*)((__half*)(dsm + LF_PB(0)) + b_n[i] * ASTRIDE + b_kc[i]) = bv[i];
        __syncthreads();

        float acc[2][8][4];
#pragma unroll
        for (int i = 0; i < 2; i++)
#pragma unroll
            for (int j = 0; j < 8; j++)
#pragma unroll
                for (int k = 0; k < 4; k++) acc[i][j][k] = 0.f;

        for (int ch = 0; ch < 8; ch++) {
            int kbase = (ch + 1) * 32;
            if (ch < 7) {
                if (kbase < 128) {
                    // h-plane prefetch
#pragma unroll
                    for (int i = 0; i < 4; i++) {
                        const __half* src = (a_plane[i] ? X1l : X1h) + (size_t)(bm + a_r[i]) * 128 + kbase + a_kc[i];
                        av[i] = (bm + a_r[i] < M) ? *(const uint4*)src : make_uint4(0u, 0u, 0u, 0u);
                    }
                } else {
                    // agg gather: warp wid handles rows wid*16..+15, lane = column c0+lane
                    const int c0 = kbase - 128;
                    float bmv = __ldg(bmsg + c0 + lane);
                    for (int j = 0; j < 16; j++) {
                        int row = bm + wid * 16 + j;
                        float a = 0.f;
                        if (row < M) {
                            int cn = g_cnt[row], of = g_off[row];
                            for (int i2 = 0; i2 < cn; i2++) {
                                int s = g_esrc[of + i2];
                                a += ABin[(size_t)s * 256 + c0 + lane];
                            }
                            float bt = ABin[(size_t)row * 256 + 128 + c0 + lane];
                            float fc = (float)cn;
                            float inv = 1.0f / fmaxf(fc, 1.0f);
                            a = (a + fc * (bt + bmv)) * inv;
                        }
                        agw[j] = __float_as_uint(a);
                    }
                }
#pragma unroll
                for (int i = 0; i < 2; i++)
                    bv[i] = *(const uint4*)(WuT + (size_t)b_n[i] * 256 + kbase + b_kc[i]);
            }
            const int st = ch & 1;
            const uint32_t sAh = smem_to_u32(dsm + LF_PAH(st));
            const uint32_t sAl = smem_to_u32(dsm + LF_PAL(st));
            const uint32_t sB  = smem_to_u32(dsm + LF_PB(st));
#pragma unroll
            for (int kk = 0; kk < 32; kk += 16) {
                uint32_t ah[2][4], al[2][4];
#pragma unroll
                for (int mt = 0; mt < 2; mt++) {
                    int r = m_off + mt * 16 + ((qq & 1) << 3) + lrow;
                    int cc = kk + ((qq >> 1) << 3);
                    uint32_t off = (uint32_t)(r * ASTRIDE + cc) * 2;
                    ldsm_x4(sAh + off, ah[mt][0], ah[mt][1], ah[mt][2], ah[mt][3]);
                    ldsm_x4(sAl + off, al[mt][0], al[mt][1], al[mt][2], al[mt][3]);
                }
#pragma unroll
                for (int np = 0; np < 4; np++) {
                    int nr = n_off + np * 16 + ((qq >> 1) << 3) + lrow;
                    int ck = kk + ((qq & 1) << 3);
                    uint32_t off = (uint32_t)(nr * ASTRIDE + ck) * 2;
                    uint32_t bh0, bh1, bh2, bh3;
                    ldsm_x4(sB + off, bh0, bh1, bh2, bh3);
#pragma unroll
                    for (int mt = 0; mt < 2; mt++) {
                        mma_f16(acc[mt][2 * np],     ah[mt], bh0, bh1);
                        mma_f16(acc[mt][2 * np],     al[mt], bh0, bh1);
                        mma_f16(acc[mt][2 * np + 1], ah[mt], bh2, bh3);
                        mma_f16(acc[mt][2 * np + 1], al[mt], bh2, bh3);
                    }
                }
            }
            if (ch < 7) {
                const int ns = (ch + 1) & 1;
                if (kbase < 128) {
#pragma unroll
                    for (int i = 0; i < 4; i++)
                        *(uint4*)((__half*)(dsm + (a_plane[i] ? LF_PAL(ns) : LF_PAH(ns))) + a_r[i] * ASTRIDE + a_kc[i]) = av[i];
                } else {
                    __half* dH = (__half*)(dsm + LF_PAH(ns));
                    __half* dL = (__half*)(dsm + LF_PAL(ns));
#pragma unroll
                    for (int j = 0; j < 16; j++) {
                        float a = __uint_as_float(agw[j]);
                        __half h, l;
                        split_f16(a, h, l);
                        int r = wid * 16 + j;
                        dH[r * ASTRIDE + lane] = h;
                        dL[r * ASTRIDE + lane] = l;
                    }
                }
#pragma unroll
                for (int i = 0; i < 2; i++)
                    *(uint4*)((__half*)(dsm + LF_PB(ns)) + b_n[i] * ASTRIDE + b_kc[i]) = bv[i];
            }
            __syncthreads();
        }

        // P1 epilogue: relu(+bias) -> SH (smem, unguarded) + gmem planes (guarded)
#pragma unroll
        for (int mt = 0; mt < 2; mt++) {
            int rl = m_off + mt * 16 + (lane >> 2);
#pragma unroll
            for (int nt = 0; nt < 8; nt++) {
                int col = n_off + nt * 8 + (lane & 3) * 2;
                float b0v = __ldg(bupd + col), b1v = __ldg(bupd + col + 1);
                float v0 = fmaxf(acc[mt][nt][0] + b0v, 0.f);
                float v1 = fmaxf(acc[mt][nt][1] + b1v, 0.f);
                float v2 = fmaxf(acc[mt][nt][2] + b0v, 0.f);
                float v3 = fmaxf(acc[mt][nt][3] + b1v, 0.f);
                __half h0, h1, l0, l1;
                uint32_t xorm = ((uint32_t)col * 2) ^ (((uint32_t)(rl & 7)) << 4);
                split_f16(v0, h0, l0); split_f16(v1, h1, l1);
                uint32_t hp = pack_h2(h0, h1), lp = pack_h2(l0, l1);
                uint32_t byte = (uint32_t)rl * 256 + xorm;
                *(uint32_t*)(dsm + LF_SH_HI + byte) = hp;
                *(uint32_t*)(dsm + LF_SH_LO + byte) = lp;
                if (bm + rl < M) {
                    *(uint32_t*)(Hh + (size_t)(bm + rl) * 128 + col) = hp;
                    *(uint32_t*)(Hl + (size_t)(bm + rl) * 128 + col) = lp;
                }
                split_f16(v2, h0, l0); split_f16(v3, h1, l1);
                hp = pack_h2(h0, h1); lp = pack_h2(l0, l1);
                byte = (uint32_t)(rl + 8) * 256 + xorm;
                *(uint32_t*)(dsm + LF_SH_HI + byte) = hp;
                *(uint32_t*)(dsm + LF_SH_LO + byte) = lp;
                if (bm + rl + 8 < M) {
                    *(uint32_t*)(Hh + (size_t)(bm + rl + 8) * 128 + col) = hp;
                    *(uint32_t*)(Hl + (size_t)(bm + rl + 8) * 128 + col) = lp;
                }
            }
        }
        __syncthreads();
    }

    // ---- P2: ABout = hn(SH) @ Wt2, two sequential 128-col halves ----
    int c_n[2], c_kc[2];
#pragma unroll
    for (int i = 0; i < 2; i++) {
        int u = i * 256 + t;
        c_n[i] = u >> 2;
        c_kc[i] = (u & 3) * 8;
    }
    for (int half = 0; half < 2; half++) {
        const __half* Wh = Wt2 + (size_t)(half * 128) * 128;
        uint4 cv[2];
#pragma unroll
        for (int i = 0; i < 2; i++)
            cv[i] = *(const uint4*)(Wh + (size_t)c_n[i] * 128 + c_kc[i]);
#pragma unroll
        for (int i = 0; i < 2; i++)
            *(uint4*)((__half*)(dsm + LF_PB(0)) + c_n[i] * ASTRIDE + c_kc[i]) = cv[i];
        __syncthreads();

        float acc2[2][8][4];
#pragma unroll
        for (int i = 0; i < 2; i++)
#pragma unroll
            for (int j = 0; j < 8; j++)
#pragma unroll
                for (int k = 0; k < 4; k++) acc2[i][j][k] = 0.f;

        for (int ch = 0; ch < 4; ch++) {
            if (ch < 3) {
                const int kbase = (ch + 1) * 32;
#pragma unroll
                for (int i = 0; i < 2; i++)
                    cv[i] = *(const uint4*)(Wh + (size_t)c_n[i] * 128 + kbase + c_kc[i]);
            }
            const uint32_t sB = smem_to_u32(dsm + LF_PB(ch & 1));
#pragma unroll
            for (int kk = 0; kk < 32; kk += 16) {
                uint32_t ah[2][4], al[2][4];
#pragma unroll
                for (int mt = 0; mt < 2; mt++) {
                    int r = m_off + mt * 16 + ((qq & 1) << 3) + lrow;
                    int c = ch * 32 + kk + ((qq >> 1) << 3);
                    uint32_t byte = (uint32_t)r * 256 + (((uint32_t)c * 2) ^ (((uint32_t)(r & 7)) << 4));
                    ldsm_x4(sSHh + byte, ah[mt][0], ah[mt][1], ah[mt][2], ah[mt][3]);
                    ldsm_x4(sSHl + byte, al[mt][0], al[mt][1], al[mt][2], al[mt][3]);
                }
#pragma unroll
                for (int np = 0; np < 4; np++) {
                    int nr = n_off + np * 16 + ((qq >> 1) << 3) + lrow;
                    int ck = kk + ((qq & 1) << 3);
                    uint32_t off = (uint32_t)(nr * ASTRIDE + ck) * 2;
                    uint32_t bh0, bh1, bh2, bh3;
                    ldsm_x4(sB + off, bh0, bh1, bh2, bh3);
#pragma unroll
                    for (int mt = 0; mt < 2; mt++) {
                        mma_f16(acc2[mt][2 * np],     ah[mt], bh0, bh1);
                        mma_f16(acc2[mt][2 * np],     al[mt], bh0, bh1);
                        mma_f16(acc2[mt][2 * np + 1], ah[mt], bh2, bh3);
                        mma_f16(acc2[mt][2 * np + 1], al[mt], bh2, bh3);
                    }
                }
            }
            if (ch < 3) {
                const int ns = (ch + 1) & 1;
#pragma unroll
                for (int i = 0; i < 2; i++)
                    *(uint4*)((__half*)(dsm + LF_PB(ns)) + c_n[i] * ASTRIDE + c_kc[i]) = cv[i];
            }
            __syncthreads();
        }

        // P2 epilogue: ABout fp32
#pragma unroll
        for (int mt = 0; mt < 2; mt++) {
            int row0 = bm + m_off + mt * 16 + (lane >> 2);
#pragma unroll
            for (int nt = 0; nt < 8; nt++) {
                int col = half * 128 + n_off + nt * 8 + (lane & 3) * 2;
                if (row0 < M)
                    *(float2*)(ABout + (size_t)row0 * 256 + col) =
                        make_float2(acc2[mt][nt][0], acc2[mt][nt][1]);
                if (row0 + 8 < M)
                    *(float2*)(ABout + (size_t)(row0 + 8) * 256 + col) =
                        make_float2(acc2[mt][nt][2], acc2[mt][nt][3]);
            }
        }
    }
}

// ================= fused edge head (unchanged) =================
#define FE_W1E   0        // 1024 f
#define FE_B1    4096     // 128 f
#define FE_WE3   4608     // 384 f
#define FE_B3    6144     // 8 f
#define FE_BE2   6176     // 64 f
#define FE_TH    6656     // 128x128 halfs, swizzled
#define FE_TL    39424
#define FE_BH    72192    // 64x128 halfs, swizzled
#define FE_SMEM  88576
#define FE_U     FE_TH    // reuse: 128 x 65 f32
#define USTRIDE  65

__global__ void __launch_bounds__(256) fused_edge_kernel(
    const float* __restrict__ PQ, const void* __restrict__ ei,
    const float* __restrict__ ea,
    const float* __restrict__ We1, const float* __restrict__ be1,
    const float* __restrict__ We2, const float* __restrict__ be2,
    const float* __restrict__ We3, const float* __restrict__ be3,
    float* __restrict__ out)
{
    extern __shared__ __align__(16) char smem[];
    float* sW1e = (float*)(smem + FE_W1E);
    float* sb1  = (float*)(smem + FE_B1);
    float* sWe3 = (float*)(smem + FE_WE3);
    float* sb3  = (float*)(smem + FE_B3);
    float* sbe2 = (float*)(smem + FE_BE2);
    const uint32_t sTh = smem_to_u32(smem + FE_TH);
    const uint32_t sTl = smem_to_u32(smem + FE_TL);
    const uint32_t sBh = smem_to_u32(smem + FE_BH);

    const int t = threadIdx.x;
    const int wid = t >> 5, lane = t & 31;
    const int e0 = blockIdx.x * 128;

    for (int i = t; i < 1024; i += 256) sW1e[i] = We1[256 * HD + i];
    if (t < 128) sb1[t] = be1[t];
    for (int i = t; i < 384; i += 256) sWe3[i] = We3[i];
    if (t < 6) sb3[t] = be3[t];
    if (t < 64) sbe2[t] = be2[t];

    for (int p = t; p < 8192; p += 256) {
        int k = p >> 6, n = p & 63;
        uint32_t byte = (uint32_t)n * 256 + (((uint32_t)k * 2) ^ (((uint32_t)(n & 7)) << 4));
        *(__half*)(smem + FE_BH + byte) = __float2half_rn(We2[p]);
    }
    __syncthreads();

    for (int pass = 0; pass < 16; pass++) {
        int e_loc = pass * 8 + wid;
        int e = e0 + e_loc;
        int s = get_idx(ei, e);
        int d = get_idx(ei, NE + e);
        float4 ea0 = *(const float4*)(ea + (size_t)e * 8);
        float4 ea1 = *(const float4*)(ea + (size_t)e * 8 + 4);
        float4 p = *(const float4*)(PQ + (size_t)s * 256 + lane * 4);
        float4 qv = *(const float4*)(PQ + (size_t)d * 256 + 128 + lane * 4);
        float4 bb = *(const float4*)(sb1 + lane * 4);
        float v[4] = {p.x + qv.x + bb.x, p.y + qv.y + bb.y,
                      p.z + qv.z + bb.z, p.w + qv.w + bb.w};
        const float eav[8] = {ea0.x, ea0.y, ea0.z, ea0.w, ea1.x, ea1.y, ea1.z, ea1.w};
#pragma unroll
        for (int j = 0; j < 8; j++) {
            float4 w = *(const float4*)(sW1e + j * 128 + lane * 4);
            v[0] += eav[j] * w.x; v[1] += eav[j] * w.y;
            v[2] += eav[j] * w.z; v[3] += eav[j] * w.w;
        }
        uint32_t hh[2], ll[2];
#pragma unroll
        for (int i = 0; i < 2; i++) {
            float a0 = fmaxf(v[2 * i], 0.f), a1 = fmaxf(v[2 * i + 1], 0.f);
            __half h0, h1, l0, l1;
            split_f16(a0, h0, l0); split_f16(a1, h1, l1);
            hh[i] = pack_h2(h0, h1);
            ll[i] = pack_h2(l0, l1);
        }
        uint32_t byte = (uint32_t)e_loc * 256 + (((uint32_t)lane * 8) ^ (((uint32_t)(e_loc & 7)) << 4));
        *(uint2*)(smem + FE_TH + byte) = make_uint2(hh[0], hh[1]);
        *(uint2*)(smem + FE_TL + byte) = make_uint2(ll[0], ll[1]);
    }
    __syncthreads();

    const int wm = wid >> 1, wn = wid & 1;
    const int m_off = wm * 32;
    const int n_off = wn * 32;
    const int lrow = lane & 7;
    const int q = lane >> 3;
    float acc[2][4][4];
#pragma unroll
    for (int i = 0; i < 2; i++)
#pragma unroll
        for (int j = 0; j < 4; j++)
#pragma unroll
            for (int k = 0; k < 4; k++) acc[i][j][k] = 0.f;

#pragma unroll
    for (int kk = 0; kk < 128; kk += 16) {
        uint32_t ah[2][4], al[2][4];
#pragma unroll
        for (int mt = 0; mt < 2; mt++) {
            int r = m_off + mt * 16 + ((q & 1) << 3) + lrow;
            int c = kk + ((q >> 1) << 3);
            uint32_t byte = (uint32_t)r * 256 + (((uint32_t)c * 2) ^ (((uint32_t)(r & 7)) << 4));
            ldsm_x4(sTh + byte, ah[mt][0], ah[mt][1], ah[mt][2], ah[mt][3]);
            ldsm_x4(sTl + byte, al[mt][0], al[mt][1], al[mt][2], al[mt][3]);
        }
#pragma unroll
        for (int np = 0; np < 2; np++) {
            int nr = n_off + np * 16 + ((q >> 1) << 3) + lrow;
            int ck = kk + ((q & 1) << 3);
            uint32_t byte = (uint32_t)nr * 256 + (((uint32_t)ck * 2) ^ (((uint32_t)(nr & 7)) << 4));
            uint32_t bh0, bh1, bh2, bh3;
            ldsm_x4(sBh + byte, bh0, bh1, bh2, bh3);
#pragma unroll
            for (int mt = 0; mt < 2; mt++) {
                mma_f16(acc[mt][2 * np],     ah[mt], bh0, bh1);
                mma_f16(acc[mt][2 * np],     al[mt], bh0, bh1);
                mma_f16(acc[mt][2 * np + 1], ah[mt], bh2, bh3);
                mma_f16(acc[mt][2 * np + 1], al[mt], bh2, bh3);
            }
        }
    }
    __syncthreads();

    float* sU = (float*)(smem + FE_U);
#pragma unroll
    for (int mt = 0; mt < 2; mt++) {
        int row0 = m_off + mt * 16 + (lane >> 2);
#pragma unroll
        for (int nt = 0; nt < 4; nt++) {
            int col = n_off + nt * 8 + (lane & 3) * 2;
            float b0 = sbe2[col], b1 = sbe2[col + 1];
            sU[row0 * USTRIDE + col]           = fmaxf(acc[mt][nt][0] + b0, 0.f);
            sU[row0 * USTRIDE + col + 1]       = fmaxf(acc[mt][nt][1] + b1, 0.f);
            sU[(row0 + 8) * USTRIDE + col]     = fmaxf(acc[mt][nt][2] + b0, 0.f);
            sU[(row0 + 8) * USTRIDE + col + 1] = fmaxf(acc[mt][nt][3] + b1, 0.f);
        }
    }
    __syncthreads();

#pragma unroll
    for (int i = 0; i < 16; i++) {
        int e_loc = wid * 16 + i;
        float u0 = sU[e_loc * USTRIDE + lane];
        float u1 = sU[e_loc * USTRIDE + 32 + lane];
        float pr[6];
#pragma unroll
        for (int c = 0; c < 6; c++)
            pr[c] = u0 * sWe3[lane * 6 + c] + u1 * sWe3[(lane + 32) * 6 + c];
#pragma unroll
        for (int c = 0; c < 6; c++)
#pragma unroll
            for (int o = 16; o; o >>= 1)
                pr[c] += __shfl_xor_sync(0xffffffffu, pr[c], o);
        if (lane == 0) {
            float* o6 = out + (size_t)(e0 + e_loc) * 6;
#pragma unroll
            for (int c = 0; c < 6; c++) o6[c] = pr[c] + sb3[c];
        }
    }
}

// ---------------- node head (reads split planes) ----------------
__global__ void node_head_kernel(const __half* __restrict__ hh, const __half* __restrict__ hl,
                                 const float* __restrict__ Wn1, const float* __restrict__ bn1,
                                 const float* __restrict__ Wn2, const float* __restrict__ bn2,
                                 float* __restrict__ out)
{
    __shared__ float sW1[HD * 64];
    __shared__ float sW2[64 * 2];
    __shared__ float sh[8][HD];
    int t = threadIdx.x;
    for (int i = t; i < HD * 64; i += 256) sW1[i] = Wn1[i];
    for (int i = t; i < 128; i += 256) sW2[i] = Wn2[i];
    __syncthreads();
    int w = t >> 5, lane = t & 31;
    float b2a = bn2[0], b2b = bn2[1];
    for (int node = blockIdx.x * 8 + w; node < NN; node += gridDim.x * 8) {
        size_t off = (size_t)node * HD + lane * 4;
        __half2 a0 = *(const __half2*)(hh + off);
        __half2 a1 = *(const __half2*)(hh + off + 2);
        __half2 c0 = *(const __half2*)(hl + off);
        __half2 c1 = *(const __half2*)(hl + off + 2);
        float2 f0 = __half22float2(a0), f1 = __half22float2(a1);
        float2 g0 = __half22float2(c0), g1 = __half22float2(c1);
        float4 hv = make_float4(f0.x + g0.x, f0.y + g0.y, f1.x + g1.x, f1.y + g1.y);
        *(float4*)(&sh[w][lane * 4]) = hv;
        __syncwarp();
        float v0 = bn1[lane], v1 = bn1[lane + 32];
#pragma unroll 8
        for (int k = 0; k < HD; k++) {
            float hk = sh[w][k];
            v0 += hk * sW1[k * 64 + lane];
            v1 += hk * sW1[k * 64 + lane + 32];
        }
        v0 = fmaxf(v0, 0.f); v1 = fmaxf(v1, 0.f);
        float p0 = v0 * sW2[lane * 2]     + v1 * sW2[(lane + 32) * 2];
        float p1 = v0 * sW2[lane * 2 + 1] + v1 * sW2[(lane + 32) * 2 + 1];
#pragma unroll
        for (int o = 16; o; o >>= 1) {
            p0 += __shfl_xor_sync(0xffffffffu, p0, o);
            p1 += __shfl_xor_sync(0xffffffffu, p1, o);
        }
        if (lane == 0) {
            out[(size_t)node * 2]     = p0 + b2a;
            out[(size_t)node * 2 + 1] = p1 + b2b;
        }
        __syncwarp();
    }
}

// ---------------- host launch ----------------
extern "C" void kernel_launch(void* const* d_in, const int* in_sizes, int n_in,
                              void* d_out, int out_size)
{
    const float* x     = (const float*)d_in[0];
    const void*  ei    = d_in[1];
    const float* ea    = (const float*)d_in[2];
    const float* W_enc = (const float*)d_in[4];
    const float* b_enc = (const float*)d_in[5];
    const float* W_msg = (const float*)d_in[6];
    const float* b_msg = (const float*)d_in[7];
    const float* W_upd = (const float*)d_in[8];
    const float* b_upd = (const float*)d_in[9];
    const float* Wn1   = (const float*)d_in[10];
    const float* bn1   = (const float*)d_in[11];
    const float* Wn2   = (const float*)d_in[12];
    const float* bn2   = (const float*)d_in[13];
    const float* We1   = (const float*)d_in[14];
    const float* be1   = (const float*)d_in[15];
    const float* We2   = (const float*)d_in[16];
    const float* be2   = (const float*)d_in[17];
    const float* We3   = (const float*)d_in[18];
    const float* be3   = (const float*)d_in[19];
    float* out = (float*)d_out;

    __half *hh0, *hl0, *hh1, *hl1, *WvT, *WpqT, *WuT;
    float *AB0, *AB1;
    cudaGetSymbolAddress((void**)&hh0, g_hh0);
    cudaGetSymbolAddress((void**)&hl0, g_hl0);
    cudaGetSymbolAddress((void**)&hh1, g_hh1);
    cudaGetSymbolAddress((void**)&hl1, g_hl1);
    cudaGetSymbolAddress((void**)&AB0, g_AB0);
    cudaGetSymbolAddress((void**)&AB1, g_AB1);
    cudaGetSymbolAddress((void**)&WvT, g_WvT);
    cudaGetSymbolAddress((void**)&WpqT, g_WpqT);
    cudaGetSymbolAddress((void**)&WuT, g_WuT);

    cudaFuncSetAttribute(fused_edge_kernel,
                         cudaFuncAttributeMaxDynamicSharedMemorySize, FE_SMEM);
    cudaFuncSetAttribute(layer_fused_kernel,
                         cudaFuncAttributeMaxDynamicSharedMemorySize, LF_SMEM);

    // dtype sniff + CSR build (parallel scan)
    detect_zero_kernel<<<(NN + 255) / 256, 256>>>(ei);
    count_kernel<<<(NE + 255) / 256, 256>>>(ei);
    scan_part_kernel<<<49, 1024>>>();
    scan_top_kernel<<<1, 64>>>();
    scan_final_kernel<<<49, 1024>>>();
    scatter_kernel<<<(NE + 255) / 256, 256>>>(ei);

    // fp16 transposed weight tables
    prep_weights_kernel<<<384, 256>>>(W_msg, We1, W_upd);

    const int MT128 = (NN + 127) / 128;   // 391

    // encoder fused with first AB = h0 @ Wv  (writes AB0)
    layer_fused_kernel<<<MT128, 256, LF_SMEM>>>(
        0, x, W_enc, b_enc,
        nullptr, nullptr, nullptr, nullptr,
        WvT, hh0, hl0, AB0, nullptr, nullptr, NN);

    // 3 GNN layers: agg fused into P1; AB ping-pong buffers
    __half *hch = hh0, *hcl = hl0, *hnh = hh1, *hnl = hl1;
    float *ABin = AB0, *ABout = AB1;
    for (int l = 0; l < 3; l++) {
        const __half* W2 = (l == 2) ? WpqT : WvT;
        layer_fused_kernel<<<MT128, 256, LF_SMEM>>>(
            1, nullptr, nullptr, nullptr,
            hch, hcl, WuT, b_upd,
            W2, hnh, hnl, ABout, ABin, b_msg, NN);
        __half* tt;
        tt = hch; hch = hnh; hnh = tt;
        tt = hcl; hcl = hnl; hnl = tt;
        float* tf = ABin; ABin = ABout; ABout = tf;
    }
    // after loop: final P|Q lives in ABin (last written)

    // node head -> out[0 : 100000)
    node_head_kernel<<<1024, 256>>>(hch, hcl, Wn1, bn1, Wn2, bn2, out);

    // edge head: ABin holds P|Q
    fused_edge_kernel<<<NE / 128, 256, FE_SMEM>>>(ABin, ei, ea, We1, be1, We2, be2, We3, be3,
                                                  out + 100000);
}

// round 17
// speedup vs baseline: 1.9516x; 1.9516x over previous
#include <cuda_runtime.h>
#include <cuda_fp16.h>
#include <cstdint>

#define NN 50000
#define NE 400000
#define HD 128

// ---------------- scratch (static device globals; no allocation) ----------------
__device__ __half g_hh0[NN * HD];
__device__ __half g_hl0[NN * HD];
__device__ __half g_hh1[NN * HD];
__device__ __half g_hl1[NN * HD];
__device__ __half g_aggh[NN * HD];
__device__ __half g_aggl[NN * HD];
__device__ float  g_AB[NN * 256];       // A|B per node (also P|Q for edge head), fp32
__device__ __half g_WvT[256 * 128];     // W_msg rearranged, fp16, [n][k]
__device__ __half g_WpqT[256 * 128];    // We1 node part, fp16, [n][k]
__device__ __half g_WuT[128 * 256];     // W_upd, fp16, [n][k]
__device__ int g_cnt[NN];
__device__ int g_off[NN];
__device__ int g_cur[NN];
__device__ int g_esrc[NE];
__device__ int g_part[64];
__device__ int g_idx64;

__device__ __forceinline__ uint32_t smem_to_u32(const void* smem_ptr) {
    uint32_t addr;
    asm("{ .reg .u64 tmp; cvta.to.shared.u64 tmp, %1; cvt.u32.u64 %0, tmp; }"
        : "=r"(addr) : "l"(smem_ptr));
    return addr;
}

// ---------------- index dtype handling (int64 vs int32 edge_index) ----------------
__device__ __forceinline__ int get_idx(const void* ei, int pos) {
    if (g_idx64) return (int)((const long long*)ei)[pos];
    return ((const int*)ei)[pos];
}

// ---------------- detect + zero counters (merged) ----------------
__global__ void detect_zero_kernel(const void* ei) {
    int i = blockIdx.x * 256 + threadIdx.x;
    if (i < NN) g_cnt[i] = 0;
    if (i == 0) {
        const long long* p = (const long long*)ei;
        int ok = 1;
        for (int j = 0; j < 64; j++) {
            long long v = p[j];
            if (v < 0 || v >= NN) { ok = 0; break; }
        }
        g_idx64 = ok;
    }
}

__global__ void count_kernel(const void* ei) {
    int e = blockIdx.x * 256 + threadIdx.x;
    if (e < NE) atomicAdd(&g_cnt[get_idx(ei, NE + e)], 1);
}

// parallel 3-phase scan over g_cnt -> g_off/g_cur  (49 blocks of 1024)
__global__ void scan_part_kernel() {
    __shared__ int sd[1024];
    int t = threadIdx.x;
    int idx = blockIdx.x * 1024 + t;
    int v = (idx < NN) ? g_cnt[idx] : 0;
    sd[t] = v; __syncthreads();
    for (int o = 512; o; o >>= 1) {
        if (t < o) sd[t] += sd[t + o];
        __syncthreads();
    }
    if (t == 0) g_part[blockIdx.x] = sd[0];
}
__global__ void scan_top_kernel() {
    __shared__ int sd[64];
    int t = threadIdx.x;
    int v = (t < 49) ? g_part[t] : 0;
    sd[t] = v; __syncthreads();
    for (int o = 1; o < 64; o <<= 1) {
        int a = (t >= o) ? sd[t - o] : 0;
        __syncthreads();
        sd[t] += a;
        __syncthreads();
    }
    if (t < 49) g_part[t] = sd[t] - v;   // exclusive prefix
}
__global__ void scan_final_kernel() {
    __shared__ int sd[1024];
    int t = threadIdx.x;
    int idx = blockIdx.x * 1024 + t;
    int v = (idx < NN) ? g_cnt[idx] : 0;
    sd[t] = v; __syncthreads();
    for (int o = 1; o < 1024; o <<= 1) {
        int a = (t >= o) ? sd[t - o] : 0;
        __syncthreads();
        sd[t] += a;
        __syncthreads();
    }
    if (idx < NN) {
        int e = sd[t] - v + g_part[blockIdx.x];
        g_off[idx] = e;
        g_cur[idx] = e;
    }
}

__global__ void scatter_kernel(const void* ei) {
    int e = blockIdx.x * 256 + threadIdx.x;
    if (e < NE) {
        int d = get_idx(ei, NE + e);
        int pos = atomicAdd(&g_cur[d], 1);
        g_esrc[pos] = get_idx(ei, e);
    }
}

// ---------------- weight prep: fp16 transposed [n][k] tables (one kernel) ----------------
__global__ void prep_weights_kernel(const float* __restrict__ W_msg,
                                    const float* __restrict__ We1,
                                    const float* __restrict__ W_upd) {
    int i = blockIdx.x * 256 + threadIdx.x;   // 0 .. 98303
    if (i < 32768) {
        int n = i >> 7, k = i & 127;
        float v = (n < 128) ? W_msg[k * 128 + n] : W_msg[(128 + k) * 128 + (n - 128)];
        g_WvT[i] = __float2half_rn(v);
    } else if (i < 65536) {
        int j = i - 32768;
        int n = j >> 7, k = j & 127;
        float v = (n < 128) ? We1[k * 128 + n] : We1[(128 + k) * 128 + (n - 128)];
        g_WpqT[j] = __float2half_rn(v);
    } else if (i < 98304) {
        int j = i - 65536;
        int n = j >> 8, k = j & 255;
        g_WuT[j] = __float2half_rn(W_upd[k * 128 + n]);
    }
}

// ---------------- MMA primitives ----------------
__device__ __forceinline__ void ldsm_x4(uint32_t addr, uint32_t& r0, uint32_t& r1,
                                        uint32_t& r2, uint32_t& r3) {
    asm volatile("ldmatrix.sync.aligned.m8n8.x4.shared.b16 {%0,%1,%2,%3}, [%4];"
                 : "=r"(r0), "=r"(r1), "=r"(r2), "=r"(r3) : "r"(addr));
}
__device__ __forceinline__ void mma_f16(float* c, const uint32_t* a, uint32_t b0, uint32_t b1) {
    asm volatile(
        "mma.sync.aligned.m16n8k16.row.col.f32.f16.f16.f32 "
        "{%0,%1,%2,%3}, {%4,%5,%6,%7}, {%8,%9}, {%0,%1,%2,%3};"
        : "+f"(c[0]), "+f"(c[1]), "+f"(c[2]), "+f"(c[3])
        : "r"(a[0]), "r"(a[1]), "r"(a[2]), "r"(a[3]), "r"(b0), "r"(b1));
}
__device__ __forceinline__ void split_f16(float v, __half& h, __half& l) {
    h = __float2half_rn(v);
    l = __float2half_rn(v - __half2float(h));
}
__device__ __forceinline__ uint32_t pack_h2(__half a, __half b) {
    return (uint32_t)__half_as_ushort(a) | ((uint32_t)__half_as_ushort(b) << 16);
}

// ================= fused layer kernel =================
// Per block: 128 node-rows.
//   P1 mode 0: hn = X0 @ W0 + b0   (encoder, K=16, scalar fp32, no relu)
//   P1 mode 1: hn = relu([X1|X2] @ WuT + bupd)   (K=256, split-fp16 mma.sync)
//   hn tile -> smem (hi/lo fp16, XOR-256B swizzle) + gmem planes Hh/Hl
//   P2: AB[128 rows][256] = hn @ Wt2   (two sequential 128-col halves)
#define ASTRIDE 40
#define LF_SH_HI  0                        // 128 x 256B swizzled (hi plane)
#define LF_SH_LO  32768                    // lo plane
#define LF_PAH(st) ((st) * 20480)          // P1 A-hi stage (overlaps SH; disjoint lifetime)
#define LF_PAL(st) ((st) * 20480 + 10240)  // P1 A-lo stage
#define LF_PB(st)  (65536 + (st) * 10240)  // B stages (P1 and P2, sequential use)
#define LF_X0  65536                       // mode 0: x tile transposed [16][128] f32
#define LF_W0  (65536 + 8192)              // mode 0: Wenc [16][128] f32
#define LF_SMEM (65536 + 20480)

__global__ void __launch_bounds__(256, 2) layer_fused_kernel(
    int mode,
    const float* __restrict__ X0, const float* __restrict__ W0, const float* __restrict__ b0,
    const __half* __restrict__ X1h, const __half* __restrict__ X1l,
    const __half* __restrict__ X2h, const __half* __restrict__ X2l,
    const __half* __restrict__ WuT, const float* __restrict__ bupd,
    const __half* __restrict__ Wt2,
    __half* __restrict__ Hh, __half* __restrict__ Hl,
    float* __restrict__ AB, int M)
{
    extern __shared__ __align__(16) char dsm[];
    const int bm = blockIdx.x * 128;
    const int t = threadIdx.x;
    const int lane = t & 31;
    const int wid = t >> 5;
    const int lrow = lane & 7, qq = lane >> 3;
    const int wm = wid >> 1, wn = wid & 1;
    const int m_off = wm * 32;
    const int n_off = wn * 64;
    const uint32_t sSHh = smem_to_u32(dsm + LF_SH_HI);
    const uint32_t sSHl = smem_to_u32(dsm + LF_SH_LO);

    if (mode == 0) {
        // ---- P1 encoder: scalar fp32, K=16, no relu ----
        float* Xs = (float*)(dsm + LF_X0);   // [16][128] transposed
        float* Ws = (float*)(dsm + LF_W0);   // [16][128]
        {
            int r = t >> 1, h8 = (t & 1) * 8;
            float4 v0 = make_float4(0.f, 0.f, 0.f, 0.f), v1 = v0;
            if (bm + r < M) {
                v0 = *(const float4*)(X0 + (size_t)(bm + r) * 16 + h8);
                v1 = *(const float4*)(X0 + (size_t)(bm + r) * 16 + h8 + 4);
            }
            Xs[(h8 + 0) * 128 + r] = v0.x; Xs[(h8 + 1) * 128 + r] = v0.y;
            Xs[(h8 + 2) * 128 + r] = v0.z; Xs[(h8 + 3) * 128 + r] = v0.w;
            Xs[(h8 + 4) * 128 + r] = v1.x; Xs[(h8 + 5) * 128 + r] = v1.y;
            Xs[(h8 + 6) * 128 + r] = v1.z; Xs[(h8 + 7) * 128 + r] = v1.w;
            int k = t >> 4, c = (t & 15) * 8;
            *(float4*)(Ws + k * 128 + c)     = *(const float4*)(W0 + (size_t)k * 128 + c);
            *(float4*)(Ws + k * 128 + c + 4) = *(const float4*)(W0 + (size_t)k * 128 + c + 4);
        }
        __syncthreads();
        const int tr = (t >> 4) * 8, tc = (t & 15) * 8;
        float acc[8][8];
#pragma unroll
        for (int i = 0; i < 8; i++)
#pragma unroll
            for (int j = 0; j < 8; j++) acc[i][j] = 0.f;
#pragma unroll
        for (int k = 0; k < 16; k++) {
            float xr[8], wc[8];
            *(float4*)(xr)     = *(const float4*)(Xs + k * 128 + tr);
            *(float4*)(xr + 4) = *(const float4*)(Xs + k * 128 + tr + 4);
            *(float4*)(wc)     = *(const float4*)(Ws + k * 128 + tc);
            *(float4*)(wc + 4) = *(const float4*)(Ws + k * 128 + tc + 4);
#pragma unroll
            for (int i = 0; i < 8; i++)
#pragma unroll
                for (int j = 0; j < 8; j++) acc[i][j] += xr[i] * wc[j];
        }
        float bj[8];
        *(float4*)(bj)     = *(const float4*)(b0 + tc);
        *(float4*)(bj + 4) = *(const float4*)(b0 + tc + 4);
#pragma unroll
        for (int i = 0; i < 8; i++) {
            int row = tr + i;
#pragma unroll
            for (int j = 0; j < 8; j += 2) {
                float v0 = acc[i][j] + bj[j], v1 = acc[i][j + 1] + bj[j + 1];
                __half h0, h1, l0, l1;
                split_f16(v0, h0, l0); split_f16(v1, h1, l1);
                uint32_t hp = pack_h2(h0, h1), lp = pack_h2(l0, l1);
                int col = tc + j;
                uint32_t byte = (uint32_t)row * 256 + (((uint32_t)col * 2) ^ (((uint32_t)(row & 7)) << 4));
                *(uint32_t*)(dsm + LF_SH_HI + byte) = hp;
                *(uint32_t*)(dsm + LF_SH_LO + byte) = lp;
                if (bm + row < M) {
                    *(uint32_t*)(Hh + (size_t)(bm + row) * 128 + col) = hp;
                    *(uint32_t*)(Hl + (size_t)(bm + row) * 128 + col) = lp;
                }
            }
        }
        __syncthreads();
    } else {
        // ---- P1 GNN layer: hn = relu([X1|X2] @ WuT + bupd), K=256, pipelined ----
        int a_plane[4], a_r[4], a_kc[4];
#pragma unroll
        for (int i = 0; i < 4; i++) {
            int u = i * 256 + t;
            a_plane[i] = u >> 9;
            a_r[i] = (u >> 2) & 127;
            a_kc[i] = (u & 3) * 8;
        }
        int b_n[2], b_kc[2];
#pragma unroll
        for (int i = 0; i < 2; i++) {
            int u = i * 256 + t;
            b_n[i] = u >> 2;
            b_kc[i] = (u & 3) * 8;
        }
        uint4 av[4], bv[2];
        // prologue chunk 0
#pragma unroll
        for (int i = 0; i < 4; i++) {
            const __half* src = (a_plane[i] ? X1l : X1h) + (size_t)(bm + a_r[i]) * 128 + a_kc[i];
            av[i] = (bm + a_r[i] < M) ? *(const uint4*)src : make_uint4(0u, 0u, 0u, 0u);
        }
#pragma unroll
        for (int i = 0; i < 2; i++)
            bv[i] = *(const uint4*)(WuT + (size_t)b_n[i] * 256 + b_kc[i]);
#pragma unroll
        for (int i = 0; i < 4; i++)
            *(uint4*)((__half*)(dsm + (a_plane[i] ? LF_PAL(0) : LF_PAH(0))) + a_r[i] * ASTRIDE + a_kc[i]) = av[i];
#pragma unroll
        for (int i = 0; i < 2; i++)
            *(uint4*)((__half*)(dsm + LF_PB(0)) + b_n[i] * ASTRIDE + b_kc[i]) = bv[i];
        __syncthreads();

        float acc[2][8][4];
#pragma unroll
        for (int i = 0; i < 2; i++)
#pragma unroll
            for (int j = 0; j < 8; j++)
#pragma unroll
                for (int k = 0; k < 4; k++) acc[i][j][k] = 0.f;

        for (int ch = 0; ch < 8; ch++) {
            if (ch < 7) {
                const int kbase = (ch + 1) * 32;
                const __half* Xh = (kbase < 128) ? X1h : X2h;
                const __half* Xl = (kbase < 128) ? X1l : X2l;
                const int col0 = kbase & 127;
#pragma unroll
                for (int i = 0; i < 4; i++) {
                    const __half* src = (a_plane[i] ? Xl : Xh) + (size_t)(bm + a_r[i]) * 128 + col0 + a_kc[i];
                    av[i] = (bm + a_r[i] < M) ? *(const uint4*)src : make_uint4(0u, 0u, 0u, 0u);
                }
#pragma unroll
                for (int i = 0; i < 2; i++)
                    bv[i] = *(const uint4*)(WuT + (size_t)b_n[i] * 256 + kbase + b_kc[i]);
            }
            const int st = ch & 1;
            const uint32_t sAh = smem_to_u32(dsm + LF_PAH(st));
            const uint32_t sAl = smem_to_u32(dsm + LF_PAL(st));
            const uint32_t sB  = smem_to_u32(dsm + LF_PB(st));
#pragma unroll
            for (int kk = 0; kk < 32; kk += 16) {
                uint32_t ah[2][4], al[2][4];
#pragma unroll
                for (int mt = 0; mt < 2; mt++) {
                    int r = m_off + mt * 16 + ((qq & 1) << 3) + lrow;
                    int cc = kk + ((qq >> 1) << 3);
                    uint32_t off = (uint32_t)(r * ASTRIDE + cc) * 2;
                    ldsm_x4(sAh + off, ah[mt][0], ah[mt][1], ah[mt][2], ah[mt][3]);
                    ldsm_x4(sAl + off, al[mt][0], al[mt][1], al[mt][2], al[mt][3]);
                }
#pragma unroll
                for (int np = 0; np < 4; np++) {
                    int nr = n_off + np * 16 + ((qq >> 1) << 3) + lrow;
                    int ck = kk + ((qq & 1) << 3);
                    uint32_t off = (uint32_t)(nr * ASTRIDE + ck) * 2;
                    uint32_t bh0, bh1, bh2, bh3;
                    ldsm_x4(sB + off, bh0, bh1, bh2, bh3);
#pragma unroll
                    for (int mt = 0; mt < 2; mt++) {
                        mma_f16(acc[mt][2 * np],     ah[mt], bh0, bh1);
                        mma_f16(acc[mt][2 * np],     al[mt], bh0, bh1);
                        mma_f16(acc[mt][2 * np + 1], ah[mt], bh2, bh3);
                        mma_f16(acc[mt][2 * np + 1], al[mt], bh2, bh3);
                    }
                }
            }
            if (ch < 7) {
                const int ns = (ch + 1) & 1;
#pragma unroll
                for (int i = 0; i < 4; i++)
                    *(uint4*)((__half*)(dsm + (a_plane[i] ? LF_PAL(ns) : LF_PAH(ns))) + a_r[i] * ASTRIDE + a_kc[i]) = av[i];
#pragma unroll
                for (int i = 0; i < 2; i++)
                    *(uint4*)((__half*)(dsm + LF_PB(ns)) + b_n[i] * ASTRIDE + b_kc[i]) = bv[i];
            }
            __syncthreads();
        }

        // P1 epilogue: relu(+bias) -> SH (smem, unguarded) + gmem planes (guarded)
#pragma unroll
        for (int mt = 0; mt < 2; mt++) {
            int rl = m_off + mt * 16 + (lane >> 2);
#pragma unroll
            for (int nt = 0; nt < 8; nt++) {
                int col = n_off + nt * 8 + (lane & 3) * 2;
                float b0v = __ldg(bupd + col), b1v = __ldg(bupd + col + 1);
                float v0 = fmaxf(acc[mt][nt][0] + b0v, 0.f);
                float v1 = fmaxf(acc[mt][nt][1] + b1v, 0.f);
                float v2 = fmaxf(acc[mt][nt][2] + b0v, 0.f);
                float v3 = fmaxf(acc[mt][nt][3] + b1v, 0.f);
                __half h0, h1, l0, l1;
                uint32_t xorm = ((uint32_t)col * 2) ^ (((uint32_t)(rl & 7)) << 4);
                split_f16(v0, h0, l0); split_f16(v1, h1, l1);
                uint32_t hp = pack_h2(h0, h1), lp = pack_h2(l0, l1);
                uint32_t byte = (uint32_t)rl * 256 + xorm;
                *(uint32_t*)(dsm + LF_SH_HI + byte) = hp;
                *(uint32_t*)(dsm + LF_SH_LO + byte) = lp;
                if (bm + rl < M) {
                    *(uint32_t*)(Hh + (size_t)(bm + rl) * 128 + col) = hp;
                    *(uint32_t*)(Hl + (size_t)(bm + rl) * 128 + col) = lp;
                }
                split_f16(v2, h0, l0); split_f16(v3, h1, l1);
                hp = pack_h2(h0, h1); lp = pack_h2(l0, l1);
                byte = (uint32_t)(rl + 8) * 256 + xorm;
                *(uint32_t*)(dsm + LF_SH_HI + byte) = hp;
                *(uint32_t*)(dsm + LF_SH_LO + byte) = lp;
                if (bm + rl + 8 < M) {
                    *(uint32_t*)(Hh + (size_t)(bm + rl + 8) * 128 + col) = hp;
                    *(uint32_t*)(Hl + (size_t)(bm + rl + 8) * 128 + col) = lp;
                }
            }
        }
        __syncthreads();
    }

    // ---- P2: AB = hn(SH) @ Wt2, two sequential 128-col halves ----
    int c_n[2], c_kc[2];
#pragma unroll
    for (int i = 0; i < 2; i++) {
        int u = i * 256 + t;
        c_n[i] = u >> 2;
        c_kc[i] = (u & 3) * 8;
    }
    for (int half = 0; half < 2; half++) {
        const __half* Wh = Wt2 + (size_t)(half * 128) * 128;
        uint4 cv[2];
#pragma unroll
        for (int i = 0; i < 2; i++)
            cv[i] = *(const uint4*)(Wh + (size_t)c_n[i] * 128 + c_kc[i]);
#pragma unroll
        for (int i = 0; i < 2; i++)
            *(uint4*)((__half*)(dsm + LF_PB(0)) + c_n[i] * ASTRIDE + c_kc[i]) = cv[i];
        __syncthreads();

        float acc2[2][8][4];
#pragma unroll
        for (int i = 0; i < 2; i++)
#pragma unroll
            for (int j = 0; j < 8; j++)
#pragma unroll
                for (int k = 0; k < 4; k++) acc2[i][j][k] = 0.f;

        for (int ch = 0; ch < 4; ch++) {
            if (ch < 3) {
                const int kbase = (ch + 1) * 32;
#pragma unroll
                for (int i = 0; i < 2; i++)
                    cv[i] = *(const uint4*)(Wh + (size_t)c_n[i] * 128 + kbase + c_kc[i]);
            }
            const uint32_t sB = smem_to_u32(dsm + LF_PB(ch & 1));
#pragma unroll
            for (int kk = 0; kk < 32; kk += 16) {
                uint32_t ah[2][4], al[2][4];
#pragma unroll
                for (int mt = 0; mt < 2; mt++) {
                    int r = m_off + mt * 16 + ((qq & 1) << 3) + lrow;
                    int c = ch * 32 + kk + ((qq >> 1) << 3);
                    uint32_t byte = (uint32_t)r * 256 + (((uint32_t)c * 2) ^ (((uint32_t)(r & 7)) << 4));
                    ldsm_x4(sSHh + byte, ah[mt][0], ah[mt][1], ah[mt][2], ah[mt][3]);
                    ldsm_x4(sSHl + byte, al[mt][0], al[mt][1], al[mt][2], al[mt][3]);
                }
#pragma unroll
                for (int np = 0; np < 4; np++) {
                    int nr = n_off + np * 16 + ((qq >> 1) << 3) + lrow;
                    int ck = kk + ((qq & 1) << 3);
                    uint32_t off = (uint32_t)(nr * ASTRIDE + ck) * 2;
                    uint32_t bh0, bh1, bh2, bh3;
                    ldsm_x4(sB + off, bh0, bh1, bh2, bh3);
#pragma unroll
                    for (int mt = 0; mt < 2; mt++) {
                        mma_f16(acc2[mt][2 * np],     ah[mt], bh0, bh1);
                        mma_f16(acc2[mt][2 * np],     al[mt], bh0, bh1);
                        mma_f16(acc2[mt][2 * np + 1], ah[mt], bh2, bh3);
                        mma_f16(acc2[mt][2 * np + 1], al[mt], bh2, bh3);
                    }
                }
            }
            if (ch < 3) {
                const int ns = (ch + 1) & 1;
#pragma unroll
                for (int i = 0; i < 2; i++)
                    *(uint4*)((__half*)(dsm + LF_PB(ns)) + c_n[i] * ASTRIDE + c_kc[i]) = cv[i];
            }
            __syncthreads();
        }

        // P2 epilogue: AB fp32
#pragma unroll
        for (int mt = 0; mt < 2; mt++) {
            int row0 = bm + m_off + mt * 16 + (lane >> 2);
#pragma unroll
            for (int nt = 0; nt < 8; nt++) {
                int col = half * 128 + n_off + nt * 8 + (lane & 3) * 2;
                if (row0 < M)
                    *(float2*)(AB + (size_t)row0 * 256 + col) =
                        make_float2(acc2[mt][nt][0], acc2[mt][nt][1]);
                if (row0 + 8 < M)
                    *(float2*)(AB + (size_t)(row0 + 8) * 256 + col) =
                        make_float2(acc2[mt][nt][2], acc2[mt][nt][3]);
            }
        }
    }
}

// ================= fused edge head (unchanged) =================
#define FE_W1E   0        // 1024 f
#define FE_B1    4096     // 128 f
#define FE_WE3   4608     // 384 f
#define FE_B3    6144     // 8 f
#define FE_BE2   6176     // 64 f
#define FE_TH    6656     // 128x128 halfs, swizzled
#define FE_TL    39424
#define FE_BH    72192    // 64x128 halfs, swizzled
#define FE_SMEM  88576
#define FE_U     FE_TH    // reuse: 128 x 65 f32
#define USTRIDE  65

__global__ void __launch_bounds__(256) fused_edge_kernel(
    const float* __restrict__ PQ, const void* __restrict__ ei,
    const float* __restrict__ ea,
    const float* __restrict__ We1, const float* __restrict__ be1,
    const float* __restrict__ We2, const float* __restrict__ be2,
    const float* __restrict__ We3, const float* __restrict__ be3,
    float* __restrict__ out)
{
    extern __shared__ __align__(16) char smem[];
    float* sW1e = (float*)(smem + FE_W1E);
    float* sb1  = (float*)(smem + FE_B1);
    float* sWe3 = (float*)(smem + FE_WE3);
    float* sb3  = (float*)(smem + FE_B3);
    float* sbe2 = (float*)(smem + FE_BE2);
    const uint32_t sTh = smem_to_u32(smem + FE_TH);
    const uint32_t sTl = smem_to_u32(smem + FE_TL);
    const uint32_t sBh = smem_to_u32(smem + FE_BH);

    const int t = threadIdx.x;
    const int wid = t >> 5, lane = t & 31;
    const int e0 = blockIdx.x * 128;

    for (int i = t; i < 1024; i += 256) sW1e[i] = We1[256 * HD + i];
    if (t < 128) sb1[t] = be1[t];
    for (int i = t; i < 384; i += 256) sWe3[i] = We3[i];
    if (t < 6) sb3[t] = be3[t];
    if (t < 64) sbe2[t] = be2[t];

    for (int p = t; p < 8192; p += 256) {
        int k = p >> 6, n = p & 63;
        uint32_t byte = (uint32_t)n * 256 + (((uint32_t)k * 2) ^ (((uint32_t)(n & 7)) << 4));
        *(__half*)(smem + FE_BH + byte) = __float2half_rn(We2[p]);
    }
    __syncthreads();

    for (int pass = 0; pass < 16; pass++) {
        int e_loc = pass * 8 + wid;
        int e = e0 + e_loc;
        int s = get_idx(ei, e);
        int d = get_idx(ei, NE + e);
        float4 ea0 = *(const float4*)(ea + (size_t)e * 8);
        float4 ea1 = *(const float4*)(ea + (size_t)e * 8 + 4);
        float4 p = *(const float4*)(PQ + (size_t)s * 256 + lane * 4);
        float4 qv = *(const float4*)(PQ + (size_t)d * 256 + 128 + lane * 4);
        float4 bb = *(const float4*)(sb1 + lane * 4);
        float v[4] = {p.x + qv.x + bb.x, p.y + qv.y + bb.y,
                      p.z + qv.z + bb.z, p.w + qv.w + bb.w};
        const float eav[8] = {ea0.x, ea0.y, ea0.z, ea0.w, ea1.x, ea1.y, ea1.z, ea1.w};
#pragma unroll
        for (int j = 0; j < 8; j++) {
            float4 w = *(const float4*)(sW1e + j * 128 + lane * 4);
            v[0] += eav[j] * w.x; v[1] += eav[j] * w.y;
            v[2] += eav[j] * w.z; v[3] += eav[j] * w.w;
        }
        uint32_t hh[2], ll[2];
#pragma unroll
        for (int i = 0; i < 2; i++) {
            float a0 = fmaxf(v[2 * i], 0.f), a1 = fmaxf(v[2 * i + 1], 0.f);
            __half h0, h1, l0, l1;
            split_f16(a0, h0, l0); split_f16(a1, h1, l1);
            hh[i] = pack_h2(h0, h1);
            ll[i] = pack_h2(l0, l1);
        }
        uint32_t byte = (uint32_t)e_loc * 256 + (((uint32_t)lane * 8) ^ (((uint32_t)(e_loc & 7)) << 4));
        *(uint2*)(smem + FE_TH + byte) = make_uint2(hh[0], hh[1]);
        *(uint2*)(smem + FE_TL + byte) = make_uint2(ll[0], ll[1]);
    }
    __syncthreads();

    const int wm = wid >> 1, wn = wid & 1;
    const int m_off = wm * 32;
    const int n_off = wn * 32;
    const int lrow = lane & 7;
    const int q = lane >> 3;
    float acc[2][4][4];
#pragma unroll
    for (int i = 0; i < 2; i++)
#pragma unroll
        for (int j = 0; j < 4; j++)
#pragma unroll
            for (int k = 0; k < 4; k++) acc[i][j][k] = 0.f;

#pragma unroll
    for (int kk = 0; kk < 128; kk += 16) {
        uint32_t ah[2][4], al[2][4];
#pragma unroll
        for (int mt = 0; mt < 2; mt++) {
            int r = m_off + mt * 16 + ((q & 1) << 3) + lrow;
            int c = kk + ((q >> 1) << 3);
            uint32_t byte = (uint32_t)r * 256 + (((uint32_t)c * 2) ^ (((uint32_t)(r & 7)) << 4));
            ldsm_x4(sTh + byte, ah[mt][0], ah[mt][1], ah[mt][2], ah[mt][3]);
            ldsm_x4(sTl + byte, al[mt][0], al[mt][1], al[mt][2], al[mt][3]);
        }
#pragma unroll
        for (int np = 0; np < 2; np++) {
            int nr = n_off + np * 16 + ((q >> 1) << 3) + lrow;
            int ck = kk + ((q & 1) << 3);
            uint32_t byte = (uint32_t)nr * 256 + (((uint32_t)ck * 2) ^ (((uint32_t)(nr & 7)) << 4));
            uint32_t bh0, bh1, bh2, bh3;
            ldsm_x4(sBh + byte, bh0, bh1, bh2, bh3);
#pragma unroll
            for (int mt = 0; mt < 2; mt++) {
                mma_f16(acc[mt][2 * np],     ah[mt], bh0, bh1);
                mma_f16(acc[mt][2 * np],     al[mt], bh0, bh1);
                mma_f16(acc[mt][2 * np + 1], ah[mt], bh2, bh3);
                mma_f16(acc[mt][2 * np + 1], al[mt], bh2, bh3);
            }
        }
    }
    __syncthreads();

    float* sU = (float*)(smem + FE_U);
#pragma unroll
    for (int mt = 0; mt < 2; mt++) {
        int row0 = m_off + mt * 16 + (lane >> 2);
#pragma unroll
        for (int nt = 0; nt < 4; nt++) {
            int col = n_off + nt * 8 + (lane & 3) * 2;
            float b0 = sbe2[col], b1 = sbe2[col + 1];
            sU[row0 * USTRIDE + col]           = fmaxf(acc[mt][nt][0] + b0, 0.f);
            sU[row0 * USTRIDE + col + 1]       = fmaxf(acc[mt][nt][1] + b1, 0.f);
            sU[(row0 + 8) * USTRIDE + col]     = fmaxf(acc[mt][nt][2] + b0, 0.f);
            sU[(row0 + 8) * USTRIDE + col + 1] = fmaxf(acc[mt][nt][3] + b1, 0.f);
        }
    }
    __syncthreads();

#pragma unroll
    for (int i = 0; i < 16; i++) {
        int e_loc = wid * 16 + i;
        float u0 = sU[e_loc * USTRIDE + lane];
        float u1 = sU[e_loc * USTRIDE + 32 + lane];
        float pr[6];
#pragma unroll
        for (int c = 0; c < 6; c++)
            pr[c] = u0 * sWe3[lane * 6 + c] + u1 * sWe3[(lane + 32) * 6 + c];
#pragma unroll
        for (int c = 0; c < 6; c++)
#pragma unroll
            for (int o = 16; o; o >>= 1)
                pr[c] += __shfl_xor_sync(0xffffffffu, pr[c], o);
        if (lane == 0) {
            float* o6 = out + (size_t)(e0 + e_loc) * 6;
#pragma unroll
            for (int c = 0; c < 6; c++) o6[c] = pr[c] + sb3[c];
        }
    }
}

// ---------------- aggregation: fp32 AB in, split fp16 planes out ----------------
// edge loop unrolled x2 (same fp32 add order; doubles memory-level parallelism)
__global__ void agg_kernel(const float* __restrict__ AB, const float* __restrict__ bmsg,
                           __half* __restrict__ aggh, __half* __restrict__ aggl)
{
    int gw = (blockIdx.x * blockDim.x + threadIdx.x) >> 5;
    int lane = threadIdx.x & 31;
    if (gw >= NN) return;
    int cnt = g_cnt[gw], off = g_off[gw];
    float4 acc = make_float4(0.f, 0.f, 0.f, 0.f);
    int i = 0;
    for (; i + 1 < cnt; i += 2) {
        int s0 = g_esrc[off + i];
        int s1 = g_esrc[off + i + 1];
        float4 a0 = *(const float4*)(AB + (size_t)s0 * 256 + lane * 4);
        float4 a1 = *(const float4*)(AB + (size_t)s1 * 256 + lane * 4);
        acc.x += a0.x; acc.y += a0.y; acc.z += a0.z; acc.w += a0.w;
        acc.x += a1.x; acc.y += a1.y; acc.z += a1.z; acc.w += a1.w;
    }
    if (i < cnt) {
        int s = g_esrc[off + i];
        float4 a = *(const float4*)(AB + (size_t)s * 256 + lane * 4);
        acc.x += a.x; acc.y += a.y; acc.z += a.z; acc.w += a.w;
    }
    float4 b = *(const float4*)(AB + (size_t)gw * 256 + 128 + lane * 4);
    float4 bm = *(const float4*)(bmsg + lane * 4);
    float fc = (float)cnt;
    float inv = 1.0f / fmaxf(fc, 1.0f);
    float r[4];
    r[0] = (acc.x + fc * (b.x + bm.x)) * inv;
    r[1] = (acc.y + fc * (b.y + bm.y)) * inv;
    r[2] = (acc.z + fc * (b.z + bm.z)) * inv;
    r[3] = (acc.w + fc * (b.w + bm.w)) * inv;
    __half h0, h1, h2, h3, l0, l1, l2, l3;
    split_f16(r[0], h0, l0); split_f16(r[1], h1, l1);
    split_f16(r[2], h2, l2); split_f16(r[3], h3, l3);
    size_t o = (size_t)gw * HD + lane * 4;
    *(uint2*)(aggh + o) = make_uint2(pack_h2(h0, h1), pack_h2(h2, h3));
    *(uint2*)(aggl + o) = make_uint2(pack_h2(l0, l1), pack_h2(l2, l3));
}

// ---------------- node head (reads split planes) ----------------
__global__ void node_head_kernel(const __half* __restrict__ hh, const __half* __restrict__ hl,
                                 const float* __restrict__ Wn1, const float* __restrict__ bn1,
                                 const float* __restrict__ Wn2, const float* __restrict__ bn2,
                                 float* __restrict__ out)
{
    __shared__ float sW1[HD * 64];
    __shared__ float sW2[64 * 2];
    __shared__ float sh[8][HD];
    int t = threadIdx.x;
    for (int i = t; i < HD * 64; i += 256) sW1[i] = Wn1[i];
    for (int i = t; i < 128; i += 256) sW2[i] = Wn2[i];
    __syncthreads();
    int w = t >> 5, lane = t & 31;
    float b2a = bn2[0], b2b = bn2[1];
    for (int node = blockIdx.x * 8 + w; node < NN; node += gridDim.x * 8) {
        size_t off = (size_t)node * HD + lane * 4;
        __half2 a0 = *(const __half2*)(hh + off);
        __half2 a1 = *(const __half2*)(hh + off + 2);
        __half2 c0 = *(const __half2*)(hl + off);
        __half2 c1 = *(const __half2*)(hl + off + 2);
        float2 f0 = __half22float2(a0), f1 = __half22float2(a1);
        float2 g0 = __half22float2(c0), g1 = __half22float2(c1);
        float4 hv = make_float4(f0.x + g0.x, f0.y + g0.y, f1.x + g1.x, f1.y + g1.y);
        *(float4*)(&sh[w][lane * 4]) = hv;
        __syncwarp();
        float v0 = bn1[lane], v1 = bn1[lane + 32];
#pragma unroll 8
        for (int k = 0; k < HD; k++) {
            float hk = sh[w][k];
            v0 += hk * sW1[k * 64 + lane];
            v1 += hk * sW1[k * 64 + lane + 32];
        }
        v0 = fmaxf(v0, 0.f); v1 = fmaxf(v1, 0.f);
        float p0 = v0 * sW2[lane * 2]     + v1 * sW2[(lane + 32) * 2];
        float p1 = v0 * sW2[lane * 2 + 1] + v1 * sW2[(lane + 32) * 2 + 1];
#pragma unroll
        for (int o = 16; o; o >>= 1) {
            p0 += __shfl_xor_sync(0xffffffffu, p0, o);
            p1 += __shfl_xor_sync(0xffffffffu, p1, o);
        }
        if (lane == 0) {
            out[(size_t)node * 2]     = p0 + b2a;
            out[(size_t)node * 2 + 1] = p1 + b2b;
        }
        __syncwarp();
    }
}

// ---------------- host launch ----------------
extern "C" void kernel_launch(void* const* d_in, const int* in_sizes, int n_in,
                              void* d_out, int out_size)
{
    const float* x     = (const float*)d_in[0];
    const void*  ei    = d_in[1];
    const float* ea    = (const float*)d_in[2];
    const float* W_enc = (const float*)d_in[4];
    const float* b_enc = (const float*)d_in[5];
    const float* W_msg = (const float*)d_in[6];
    const float* b_msg = (const float*)d_in[7];
    const float* W_upd = (const float*)d_in[8];
    const float* b_upd = (const float*)d_in[9];
    const float* Wn1   = (const float*)d_in[10];
    const float* bn1   = (const float*)d_in[11];
    const float* Wn2   = (const float*)d_in[12];
    const float* bn2   = (const float*)d_in[13];
    const float* We1   = (const float*)d_in[14];
    const float* be1   = (const float*)d_in[15];
    const float* We2   = (const float*)d_in[16];
    const float* be2   = (const float*)d_in[17];
    const float* We3   = (const float*)d_in[18];
    const float* be3   = (const float*)d_in[19];
    float* out = (float*)d_out;

    __half *hh0, *hl0, *hh1, *hl1, *aggh, *aggl, *WvT, *WpqT, *WuT;
    float *AB;
    cudaGetSymbolAddress((void**)&hh0, g_hh0);
    cudaGetSymbolAddress((void**)&hl0, g_hl0);
    cudaGetSymbolAddress((void**)&hh1, g_hh1);
    cudaGetSymbolAddress((void**)&hl1, g_hl1);
    cudaGetSymbolAddress((void**)&aggh, g_aggh);
    cudaGetSymbolAddress((void**)&aggl, g_aggl);
    cudaGetSymbolAddress((void**)&AB, g_AB);
    cudaGetSymbolAddress((void**)&WvT, g_WvT);
    cudaGetSymbolAddress((void**)&WpqT, g_WpqT);
    cudaGetSymbolAddress((void**)&WuT, g_WuT);

    cudaFuncSetAttribute(fused_edge_kernel,
                         cudaFuncAttributeMaxDynamicSharedMemorySize, FE_SMEM);
    cudaFuncSetAttribute(layer_fused_kernel,
                         cudaFuncAttributeMaxDynamicSharedMemorySize, LF_SMEM);

    // dtype sniff + CSR build (parallel scan)
    detect_zero_kernel<<<(NN + 255) / 256, 256>>>(ei);
    count_kernel<<<(NE + 255) / 256, 256>>>(ei);
    scan_part_kernel<<<49, 1024>>>();
    scan_top_kernel<<<1, 64>>>();
    scan_final_kernel<<<49, 1024>>>();
    scatter_kernel<<<(NE + 255) / 256, 256>>>(ei);

    // fp16 transposed weight tables
    prep_weights_kernel<<<384, 256>>>(W_msg, We1, W_upd);

    const int MT128 = (NN + 127) / 128;   // 391

    // encoder fused with first AB = h0 @ Wv
    layer_fused_kernel<<<MT128, 256, LF_SMEM>>>(
        0, x, W_enc, b_enc,
        nullptr, nullptr, nullptr, nullptr, nullptr, nullptr,
        WvT, hh0, hl0, AB, NN);

    // 3 GNN layers: agg, then fused [h,agg]@Wu (+relu) and AB = hn @ (Wv or Wpq)
    __half *hch = hh0, *hcl = hl0, *hnh = hh1, *hnl = hl1;
    for (int l = 0; l < 3; l++) {
        agg_kernel<<<(NN * 32 + 255) / 256, 256>>>(AB, b_msg, aggh, aggl);
        const __half* W2 = (l == 2) ? WpqT : WvT;
        layer_fused_kernel<<<MT128, 256, LF_SMEM>>>(
            1, nullptr, nullptr, nullptr,
            hch, hcl, aggh, aggl, WuT, b_upd,
            W2, hnh, hnl, AB, NN);
        __half* tt;
        tt = hch; hch = hnh; hnh = tt;
        tt = hcl; hcl = hnl; hnl = tt;
    }

    // node head -> out[0 : 100000)
    node_head_kernel<<<1024, 256>>>(hch, hcl, Wn1, bn1, Wn2, bn2, out);

    // edge head: AB now holds P|Q
    fused_edge_kernel<<<NE / 128, 256, FE_SMEM>>>(AB, ei, ea, We1, be1, We2, be2, We3, be3,
                                                  out + 100000);
}